// round 5
// baseline (speedup 1.0000x reference)
#include <cuda_runtime.h>
#include <math.h>

#define B_SZ     2
#define SEQ_L    2048
#define D_MODEL  1024
#define D_INNER  2048
#define D_STATE  16
#define D_CONV   4
#define DT_RANK  64
#define M_TOT    (B_SZ * SEQ_L)              // 4096
#define XD       (DT_RANK + 2 * D_STATE)     // 96

// ---------------------------------------------------------------------------
// Scratch (device globals — no allocation allowed in kernel_launch)
// ---------------------------------------------------------------------------
__device__ float g_c1[(size_t)M_TOT * 2 * D_INNER];   // xr = [u_pre | res], 64MB
__device__ float g_uconv[(size_t)M_TOT * D_INNER];    // conv+silu output, 32MB
__device__ float g_xdbl[(size_t)M_TOT * XD];          // [dt_low | B | C]
__device__ float g_dt[(size_t)M_TOT * D_INNER];       // softplus(dt), 32MB
__device__ float g_y[(size_t)M_TOT * D_INNER];        // scan y -> combined y, 32MB

// ---------------------------------------------------------------------------
// Generic fp32 SIMT GEMM: C[M,N] = A[M,K] @ B[K,N]  (all row-major)
// BM=BN=128, BK=16, 256 threads, 8x8 per thread.
// mode 0: plain store.  mode 1: softplus(acc + bias[n]).
// Requires: M % 128 == 0, K % 16 == 0. N arbitrary (guarded).
// ---------------------------------------------------------------------------
#define BM 128
#define BN 128
#define BK 16
#define TM 8
#define TN 8

__global__ __launch_bounds__(256) void gemm_kernel(
    const float* __restrict__ A, const float* __restrict__ B, float* __restrict__ C,
    int M, int N, int K, int lda, int ldb, int ldc,
    const float* __restrict__ bias, int mode)
{
    __shared__ float As[BK][BM];
    __shared__ float Bs[BK][BN];

    const int tid  = threadIdx.x;
    const int row0 = blockIdx.y * BM;
    const int col0 = blockIdx.x * BN;

    // A tile load mapping: 2 x float4 per thread
    const int a_r = tid >> 2;          // 0..63
    const int a_c = (tid & 3) * 4;     // 0,4,8,12
    // B tile load mapping: 2 x float4 per thread
    const int b_r = tid >> 5;          // 0..7
    const int b_c = (tid & 31) * 4;    // 0..124

    const int tr = (tid >> 4) * TM;    // output row within tile
    const int tc = (tid & 15) * TN;    // output col within tile

    float acc[TM][TN];
    #pragma unroll
    for (int i = 0; i < TM; i++)
        #pragma unroll
        for (int j = 0; j < TN; j++) acc[i][j] = 0.0f;

    for (int k0 = 0; k0 < K; k0 += BK) {
        // load A tile (store transposed: As[k][m])
        #pragma unroll
        for (int i = 0; i < 2; i++) {
            int r = a_r + i * 64;
            float4 v = *(const float4*)(A + (size_t)(row0 + r) * lda + k0 + a_c);
            As[a_c + 0][r] = v.x;
            As[a_c + 1][r] = v.y;
            As[a_c + 2][r] = v.z;
            As[a_c + 3][r] = v.w;
        }
        // load B tile
        #pragma unroll
        for (int i = 0; i < 2; i++) {
            int r = b_r + i * 8;
            float4 v = make_float4(0.f, 0.f, 0.f, 0.f);
            if (col0 + b_c < N)
                v = *(const float4*)(B + (size_t)(k0 + r) * ldb + col0 + b_c);
            *(float4*)(&Bs[r][b_c]) = v;
        }
        __syncthreads();

        #pragma unroll
        for (int k = 0; k < BK; k++) {
            float am[TM], bn[TN];
            #pragma unroll
            for (int i = 0; i < TM; i += 4)
                *(float4*)(am + i) = *(const float4*)(&As[k][tr + i]);
            #pragma unroll
            for (int j = 0; j < TN; j += 4)
                *(float4*)(bn + j) = *(const float4*)(&Bs[k][tc + j]);
            #pragma unroll
            for (int i = 0; i < TM; i++)
                #pragma unroll
                for (int j = 0; j < TN; j++)
                    acc[i][j] = fmaf(am[i], bn[j], acc[i][j]);
        }
        __syncthreads();
    }

    // epilogue
    #pragma unroll
    for (int i = 0; i < TM; i++) {
        const int r = row0 + tr + i;
        #pragma unroll
        for (int j = 0; j < TN; j++) {
            const int c = col0 + tc + j;
            if (c < N) {
                float v = acc[i][j];
                if (mode == 1) {
                    v += bias[c];
                    // softplus with overflow guard
                    v = (v > 20.0f) ? v : log1pf(__expf(v));
                }
                C[(size_t)r * ldc + c] = v;
            }
        }
    }
}

// ---------------------------------------------------------------------------
// Causal depthwise conv (kernel 4) + bias + silu.
// Reads u_pre from g_c1 columns [0, D_INNER), writes g_uconv.
// ---------------------------------------------------------------------------
__global__ void conv_silu_kernel(const float* __restrict__ c1,
                                 const float* __restrict__ w,
                                 const float* __restrict__ bias,
                                 float* __restrict__ out)
{
    int idx = blockIdx.x * blockDim.x + threadIdx.x;
    if (idx >= M_TOT * D_INNER) return;
    const int d = idx & (D_INNER - 1);
    const int m = idx >> 11;           // D_INNER = 2048 = 2^11
    const int l = m & (SEQ_L - 1);
    const float* up = c1 + (size_t)(m - l) * (2 * D_INNER) + d; // batch base
    float acc = bias[d];
    #pragma unroll
    for (int k = 0; k < D_CONV; k++) {
        int ll = l + k - (D_CONV - 1);
        if (ll >= 0)
            acc = fmaf(up[(size_t)ll * (2 * D_INNER)], w[d * D_CONV + k], acc);
    }
    out[idx] = acc * (1.0f / (1.0f + __expf(-acc)));   // silu
}

// ---------------------------------------------------------------------------
// Selective scan. 16 lanes per channel (lane = state index), 2 channels/warp,
// 16 channels per 256-thread block. Software-pipelined: dA/dBu for step l+1
// are computed while step l's h-update + reduction retire.
// ---------------------------------------------------------------------------
__global__ __launch_bounds__(256) void scan_kernel(
    const float* __restrict__ xdbl, const float* __restrict__ dt,
    const float* __restrict__ u, const float* __restrict__ A_log,
    float* __restrict__ y)
{
    const int c = blockIdx.x * 16 + (threadIdx.x >> 4);  // channel 0..4095
    const int s = threadIdx.x & 15;                      // state index
    const int b = c >> 11;
    const int d = c & (D_INNER - 1);

    const float A = -__expf(A_log[d * D_STATE + s]);

    const float* dtp = dt   + (size_t)b * SEQ_L * D_INNER + d;
    const float* up  = u    + (size_t)b * SEQ_L * D_INNER + d;
    const float* xp  = xdbl + (size_t)b * SEQ_L * XD + DT_RANK + s;
    float*       yp  = y    + (size_t)b * SEQ_L * D_INNER + d;

    float h = 0.0f;

    // prologue: step 0 inputs
    float dtv = dtp[0];
    float uv  = up[0];
    float Bv  = xp[0];
    float Cv  = xp[D_STATE];
    float dA  = __expf(dtv * A);
    float dBu = dtv * Bv * uv;

    for (int l = 0; l < SEQ_L; l++) {
        // prefetch step l+1 (independent of h chain)
        float dt2 = 0.f, u2 = 0.f, B2 = 0.f, C2 = 0.f;
        if (l + 1 < SEQ_L) {
            size_t o = (size_t)(l + 1);
            dt2 = dtp[o * D_INNER];
            u2  = up [o * D_INNER];
            B2  = xp [o * XD];
            C2  = xp [o * XD + D_STATE];
        }
        // recurrence (serial chain = 1 FFMA)
        h = fmaf(dA, h, dBu);
        float p = h * Cv;
        // reduce over 16 states (xor stays within aligned 16-lane group)
        p += __shfl_xor_sync(0xffffffffu, p, 8);
        p += __shfl_xor_sync(0xffffffffu, p, 4);
        p += __shfl_xor_sync(0xffffffffu, p, 2);
        p += __shfl_xor_sync(0xffffffffu, p, 1);
        if (s == 0) yp[(size_t)l * D_INNER] = p;
        // next step's independent work
        dA  = __expf(dt2 * A);
        dBu = dt2 * B2 * u2;
        Cv  = C2;
    }
}

// ---------------------------------------------------------------------------
// y = (y_scan + u*D) * silu(res)   (in-place on g_y)
// ---------------------------------------------------------------------------
__global__ void combine_kernel(const float* __restrict__ c1,
                               const float* __restrict__ uconv,
                               const float* __restrict__ Dp,
                               float* __restrict__ y)
{
    int idx = blockIdx.x * blockDim.x + threadIdx.x;
    if (idx >= M_TOT * D_INNER) return;
    const int d = idx & (D_INNER - 1);
    const int m = idx >> 11;
    const float res = c1[(size_t)m * (2 * D_INNER) + D_INNER + d];
    const float sres = res * (1.0f / (1.0f + __expf(-res)));
    y[idx] = (y[idx] + uconv[idx] * Dp[d]) * sres;
}

// ---------------------------------------------------------------------------
// Launch
// ---------------------------------------------------------------------------
extern "C" void kernel_launch(void* const* d_in, const int* in_sizes, int n_in,
                              void* d_out, int out_size)
{
    const float* x       = (const float*)d_in[0];
    const float* W_in    = (const float*)d_in[1];
    const float* conv_w  = (const float*)d_in[2];
    const float* conv_b  = (const float*)d_in[3];
    const float* W_xproj = (const float*)d_in[4];
    const float* W_dt    = (const float*)d_in[5];
    const float* b_dt    = (const float*)d_in[6];
    const float* A_log   = (const float*)d_in[7];
    const float* Dp      = (const float*)d_in[8];
    const float* W_out   = (const float*)d_in[9];
    float* out = (float*)d_out;

    float *c1, *uconv, *xdbl, *dtb, *yb;
    cudaGetSymbolAddress((void**)&c1,    g_c1);
    cudaGetSymbolAddress((void**)&uconv, g_uconv);
    cudaGetSymbolAddress((void**)&xdbl,  g_xdbl);
    cudaGetSymbolAddress((void**)&dtb,   g_dt);
    cudaGetSymbolAddress((void**)&yb,    g_y);

    dim3 blk(256);

    // 1) xr = x @ W_in  -> g_c1  [4096 x 4096]
    {
        dim3 grid((2 * D_INNER) / BN, M_TOT / BM);
        gemm_kernel<<<grid, blk>>>(x, W_in, c1,
                                   M_TOT, 2 * D_INNER, D_MODEL,
                                   D_MODEL, 2 * D_INNER, 2 * D_INNER,
                                   nullptr, 0);
    }

    // 2) causal conv + silu -> g_uconv
    {
        int total = M_TOT * D_INNER;
        conv_silu_kernel<<<(total + 255) / 256, blk>>>(c1, conv_w, conv_b, uconv);
    }

    // 3) x_dbl = uconv @ W_xproj -> g_xdbl  [4096 x 96]
    {
        dim3 grid((XD + BN - 1) / BN, M_TOT / BM);
        gemm_kernel<<<grid, blk>>>(uconv, W_xproj, xdbl,
                                   M_TOT, XD, D_INNER,
                                   D_INNER, XD, XD,
                                   nullptr, 0);
    }

    // 4) dt = softplus(dt_low @ W_dt + b_dt) -> g_dt  [4096 x 2048]
    {
        dim3 grid(D_INNER / BN, M_TOT / BM);
        gemm_kernel<<<grid, blk>>>(xdbl, W_dt, dtb,
                                   M_TOT, D_INNER, DT_RANK,
                                   XD, D_INNER, D_INNER,
                                   b_dt, 1);
    }

    // 5) selective scan -> g_y
    {
        scan_kernel<<<(B_SZ * D_INNER) / 16, blk>>>(xdbl, dtb, uconv, A_log, yb);
    }

    // 6) combine: y = (y + u*D) * silu(res)  (in-place)
    {
        int total = M_TOT * D_INNER;
        combine_kernel<<<(total + 255) / 256, blk>>>(c1, uconv, Dp, yb);
    }

    // 7) out = y @ W_out  [4096 x 1024]
    {
        dim3 grid(D_MODEL / BN, M_TOT / BM);
        gemm_kernel<<<grid, blk>>>(yb, W_out, out,
                                   M_TOT, D_MODEL, D_INNER,
                                   D_INNER, D_MODEL, D_MODEL,
                                   nullptr, 0);
    }
}

// round 6
// speedup vs baseline: 1.1991x; 1.1991x over previous
#include <cuda_runtime.h>
#include <math.h>

#define B_SZ     2
#define SEQ_L    2048
#define D_MODEL  1024
#define D_INNER  2048
#define D_STATE  16
#define D_CONV   4
#define DT_RANK  64
#define M_TOT    (B_SZ * SEQ_L)              // 4096
#define XD       (DT_RANK + 2 * D_STATE)     // 96

// ---------------------------------------------------------------------------
// Scratch (device globals — no allocation allowed in kernel_launch)
// ---------------------------------------------------------------------------
__device__ float g_c1[(size_t)M_TOT * 2 * D_INNER];   // xr = [u_pre | res]
__device__ float g_uconv[(size_t)M_TOT * D_INNER];    // conv+silu output
__device__ float g_xdbl[(size_t)M_TOT * XD];          // [dt_low | B | C]
__device__ float g_dt[(size_t)M_TOT * D_INNER];       // softplus(dt)
__device__ float g_y[(size_t)M_TOT * D_INNER];        // scan y -> combined y

// ---------------------------------------------------------------------------
// fp32 SIMT GEMM with packed f32x2 FFMA (FFMA2), double-buffered SMEM,
// conflict-free fragment mapping.
//   C[M,N] = A[M,K] @ B[K,N]  (row-major)
//   BM=BN=128, BK=16, 256 threads, 8x8 per thread (4+4 split).
//   mode 0: plain store.  mode 1: softplus(acc + bias[n]).
//   Requires: M % 128 == 0, K % 16 == 0, N % 4 == 0 (guarded per float2).
// ---------------------------------------------------------------------------
#define BM 128
#define BN 128
#define BK 16

__global__ __launch_bounds__(256) void gemm_kernel(
    const float* __restrict__ A, const float* __restrict__ B, float* __restrict__ C,
    int M, int N, int K, int lda, int ldb, int ldc,
    const float* __restrict__ bias, int mode)
{
    __shared__ float As[2][BK][BM];
    __shared__ float Bs[2][BK][BN];

    const int tid  = threadIdx.x;
    const int row0 = blockIdx.y * BM;
    const int col0 = blockIdx.x * BN;

    // global A tile load mapping: 2 x float4 per thread
    const int a_r = tid >> 2;          // 0..63
    const int a_c = (tid & 3) * 4;     // 0,4,8,12
    // global B tile load mapping: 2 x float4 per thread
    const int b_r = tid >> 5;          // 0..7
    const int b_c = (tid & 31) * 4;    // 0..124

    // fragment mapping: 4+4 split — rows {tr..tr+3, tr+64..tr+67},
    // cols {tc..tc+3, tc+64..tc+67}. Conflict-free LDS.128.
    const int tr = (tid >> 4) * 4;     // 0..60
    const int tc = (tid & 15) * 4;     // 0..60

    // accumulators: 8 rows x 4 f32x2 pairs (= 8 cols)
    unsigned long long acc[8][4];
    #pragma unroll
    for (int i = 0; i < 8; i++)
        #pragma unroll
        for (int j = 0; j < 4; j++) acc[i][j] = 0ull;

    const bool bok = (col0 + b_c) < N;
    const float* Ap0 = A + (size_t)(row0 + a_r) * lda + a_c;
    const float* Ap1 = Ap0 + (size_t)64 * lda;
    const float* Bp0 = B + (size_t)b_r * ldb + col0 + b_c;
    const float* Bp1 = Bp0 + (size_t)8 * ldb;

    float4 pa0, pa1, pb0, pb1;
    const float4 fz = make_float4(0.f, 0.f, 0.f, 0.f);

    // prologue: tile k0=0 -> buffer 0
    pa0 = *(const float4*)(Ap0);
    pa1 = *(const float4*)(Ap1);
    pb0 = bok ? *(const float4*)(Bp0) : fz;
    pb1 = bok ? *(const float4*)(Bp1) : fz;
    {
        As[0][a_c + 0][a_r]      = pa0.x;
        As[0][a_c + 1][a_r]      = pa0.y;
        As[0][a_c + 2][a_r]      = pa0.z;
        As[0][a_c + 3][a_r]      = pa0.w;
        As[0][a_c + 0][a_r + 64] = pa1.x;
        As[0][a_c + 1][a_r + 64] = pa1.y;
        As[0][a_c + 2][a_r + 64] = pa1.z;
        As[0][a_c + 3][a_r + 64] = pa1.w;
        *(float4*)(&Bs[0][b_r][b_c])     = pb0;
        *(float4*)(&Bs[0][b_r + 8][b_c]) = pb1;
    }
    __syncthreads();

    int cur = 0;
    for (int k0 = BK; k0 < K; k0 += BK) {
        // prefetch next tile into registers
        pa0 = *(const float4*)(Ap0 + k0);
        pa1 = *(const float4*)(Ap1 + k0);
        pb0 = bok ? *(const float4*)(Bp0 + (size_t)k0 * ldb) : fz;
        pb1 = bok ? *(const float4*)(Bp1 + (size_t)k0 * ldb) : fz;

        // compute current buffer
        #pragma unroll
        for (int k = 0; k < BK; k++) {
            float4 a0 = *(const float4*)(&As[cur][k][tr]);
            float4 a1 = *(const float4*)(&As[cur][k][tr + 64]);
            float4 b0 = *(const float4*)(&Bs[cur][k][tc]);
            float4 b1 = *(const float4*)(&Bs[cur][k][tc + 64]);
            unsigned long long bb[4];
            bb[0] = *((const unsigned long long*)&b0 + 0);
            bb[1] = *((const unsigned long long*)&b0 + 1);
            bb[2] = *((const unsigned long long*)&b1 + 0);
            bb[3] = *((const unsigned long long*)&b1 + 1);
            float av[8] = {a0.x, a0.y, a0.z, a0.w, a1.x, a1.y, a1.z, a1.w};
            #pragma unroll
            for (int i = 0; i < 8; i++) {
                unsigned long long a2;
                asm("mov.b64 %0, {%1, %1};" : "=l"(a2) : "r"(__float_as_uint(av[i])));
                #pragma unroll
                for (int j = 0; j < 4; j++)
                    asm("fma.rn.f32x2 %0, %1, %2, %0;"
                        : "+l"(acc[i][j]) : "l"(a2), "l"(bb[j]));
            }
        }

        // store prefetched tile into the other buffer
        {
            int nb = cur ^ 1;
            As[nb][a_c + 0][a_r]      = pa0.x;
            As[nb][a_c + 1][a_r]      = pa0.y;
            As[nb][a_c + 2][a_r]      = pa0.z;
            As[nb][a_c + 3][a_r]      = pa0.w;
            As[nb][a_c + 0][a_r + 64] = pa1.x;
            As[nb][a_c + 1][a_r + 64] = pa1.y;
            As[nb][a_c + 2][a_r + 64] = pa1.z;
            As[nb][a_c + 3][a_r + 64] = pa1.w;
            *(float4*)(&Bs[nb][b_r][b_c])     = pb0;
            *(float4*)(&Bs[nb][b_r + 8][b_c]) = pb1;
        }
        __syncthreads();
        cur ^= 1;
    }

    // final tile compute
    #pragma unroll
    for (int k = 0; k < BK; k++) {
        float4 a0 = *(const float4*)(&As[cur][k][tr]);
        float4 a1 = *(const float4*)(&As[cur][k][tr + 64]);
        float4 b0 = *(const float4*)(&Bs[cur][k][tc]);
        float4 b1 = *(const float4*)(&Bs[cur][k][tc + 64]);
        unsigned long long bb[4];
        bb[0] = *((const unsigned long long*)&b0 + 0);
        bb[1] = *((const unsigned long long*)&b0 + 1);
        bb[2] = *((const unsigned long long*)&b1 + 0);
        bb[3] = *((const unsigned long long*)&b1 + 1);
        float av[8] = {a0.x, a0.y, a0.z, a0.w, a1.x, a1.y, a1.z, a1.w};
        #pragma unroll
        for (int i = 0; i < 8; i++) {
            unsigned long long a2;
            asm("mov.b64 %0, {%1, %1};" : "=l"(a2) : "r"(__float_as_uint(av[i])));
            #pragma unroll
            for (int j = 0; j < 4; j++)
                asm("fma.rn.f32x2 %0, %1, %2, %0;"
                    : "+l"(acc[i][j]) : "l"(a2), "l"(bb[j]));
        }
    }

    // epilogue: unpack pairs, apply mode, store as float2 (N % 4 == 0)
    union F2 { unsigned long long u; float f[2]; };
    #pragma unroll
    for (int i = 0; i < 8; i++) {
        const int r = row0 + tr + ((i < 4) ? i : (60 + i));   // i>=4 -> tr+64+(i-4)
        #pragma unroll
        for (int j2 = 0; j2 < 4; j2++) {
            const int cbase = col0 + ((j2 < 2) ? (tc + j2 * 2)
                                               : (tc + 64 + (j2 - 2) * 2));
            if (cbase < N) {
                F2 v; v.u = acc[i][j2];
                if (mode == 1) {
                    #pragma unroll
                    for (int e = 0; e < 2; e++) {
                        float val = v.f[e] + bias[cbase + e];
                        v.f[e] = (val > 20.0f) ? val : log1pf(__expf(val));
                    }
                }
                *(float2*)(C + (size_t)r * ldc + cbase) = make_float2(v.f[0], v.f[1]);
            }
        }
    }
}

// ---------------------------------------------------------------------------
// Causal depthwise conv (kernel 4) + bias + silu.
// ---------------------------------------------------------------------------
__global__ void conv_silu_kernel(const float* __restrict__ c1,
                                 const float* __restrict__ w,
                                 const float* __restrict__ bias,
                                 float* __restrict__ out)
{
    int idx = blockIdx.x * blockDim.x + threadIdx.x;
    if (idx >= M_TOT * D_INNER) return;
    const int d = idx & (D_INNER - 1);
    const int m = idx >> 11;
    const int l = m & (SEQ_L - 1);
    const float* up = c1 + (size_t)(m - l) * (2 * D_INNER) + d;
    float acc = bias[d];
    #pragma unroll
    for (int k = 0; k < D_CONV; k++) {
        int ll = l + k - (D_CONV - 1);
        if (ll >= 0)
            acc = fmaf(up[(size_t)ll * (2 * D_INNER)], w[d * D_CONV + k], acc);
    }
    out[idx] = acc * (1.0f / (1.0f + __expf(-acc)));
}

// ---------------------------------------------------------------------------
// Selective scan. 16 lanes per channel, 2 channels/warp, pipelined.
// ---------------------------------------------------------------------------
__global__ __launch_bounds__(256) void scan_kernel(
    const float* __restrict__ xdbl, const float* __restrict__ dt,
    const float* __restrict__ u, const float* __restrict__ A_log,
    float* __restrict__ y)
{
    const int c = blockIdx.x * 16 + (threadIdx.x >> 4);
    const int s = threadIdx.x & 15;
    const int b = c >> 11;
    const int d = c & (D_INNER - 1);

    const float A = -__expf(A_log[d * D_STATE + s]);

    const float* dtp = dt   + (size_t)b * SEQ_L * D_INNER + d;
    const float* up  = u    + (size_t)b * SEQ_L * D_INNER + d;
    const float* xp  = xdbl + (size_t)b * SEQ_L * XD + DT_RANK + s;
    float*       yp  = y    + (size_t)b * SEQ_L * D_INNER + d;

    float h = 0.0f;

    float dtv = dtp[0];
    float uv  = up[0];
    float Bv  = xp[0];
    float Cv  = xp[D_STATE];
    float dA  = __expf(dtv * A);
    float dBu = dtv * Bv * uv;
    (void)uv;

    for (int l = 0; l < SEQ_L; l++) {
        float dt2 = 0.f, u2 = 0.f, B2 = 0.f, C2 = 0.f;
        if (l + 1 < SEQ_L) {
            size_t o = (size_t)(l + 1);
            dt2 = dtp[o * D_INNER];
            u2  = up [o * D_INNER];
            B2  = xp [o * XD];
            C2  = xp [o * XD + D_STATE];
        }
        h = fmaf(dA, h, dBu);
        float p = h * Cv;
        p += __shfl_xor_sync(0xffffffffu, p, 8);
        p += __shfl_xor_sync(0xffffffffu, p, 4);
        p += __shfl_xor_sync(0xffffffffu, p, 2);
        p += __shfl_xor_sync(0xffffffffu, p, 1);
        if (s == 0) yp[(size_t)l * D_INNER] = p;
        dA  = __expf(dt2 * A);
        dBu = dt2 * B2 * u2;
        Cv  = C2;
    }
}

// ---------------------------------------------------------------------------
// y = (y_scan + u*D) * silu(res)
// ---------------------------------------------------------------------------
__global__ void combine_kernel(const float* __restrict__ c1,
                               const float* __restrict__ uconv,
                               const float* __restrict__ Dp,
                               float* __restrict__ y)
{
    int idx = blockIdx.x * blockDim.x + threadIdx.x;
    if (idx >= M_TOT * D_INNER) return;
    const int d = idx & (D_INNER - 1);
    const int m = idx >> 11;
    const float res = c1[(size_t)m * (2 * D_INNER) + D_INNER + d];
    const float sres = res * (1.0f / (1.0f + __expf(-res)));
    y[idx] = (y[idx] + uconv[idx] * Dp[d]) * sres;
}

// ---------------------------------------------------------------------------
// Launch
// ---------------------------------------------------------------------------
extern "C" void kernel_launch(void* const* d_in, const int* in_sizes, int n_in,
                              void* d_out, int out_size)
{
    const float* x       = (const float*)d_in[0];
    const float* W_in    = (const float*)d_in[1];
    const float* conv_w  = (const float*)d_in[2];
    const float* conv_b  = (const float*)d_in[3];
    const float* W_xproj = (const float*)d_in[4];
    const float* W_dt    = (const float*)d_in[5];
    const float* b_dt    = (const float*)d_in[6];
    const float* A_log   = (const float*)d_in[7];
    const float* Dp      = (const float*)d_in[8];
    const float* W_out   = (const float*)d_in[9];
    float* out = (float*)d_out;

    float *c1, *uconv, *xdbl, *dtb, *yb;
    cudaGetSymbolAddress((void**)&c1,    g_c1);
    cudaGetSymbolAddress((void**)&uconv, g_uconv);
    cudaGetSymbolAddress((void**)&xdbl,  g_xdbl);
    cudaGetSymbolAddress((void**)&dtb,   g_dt);
    cudaGetSymbolAddress((void**)&yb,    g_y);

    dim3 blk(256);

    // 1) xr = x @ W_in  [4096 x 4096 x 1024]
    {
        dim3 grid((2 * D_INNER) / BN, M_TOT / BM);
        gemm_kernel<<<grid, blk>>>(x, W_in, c1,
                                   M_TOT, 2 * D_INNER, D_MODEL,
                                   D_MODEL, 2 * D_INNER, 2 * D_INNER,
                                   nullptr, 0);
    }

    // 2) causal conv + silu
    {
        int total = M_TOT * D_INNER;
        conv_silu_kernel<<<(total + 255) / 256, blk>>>(c1, conv_w, conv_b, uconv);
    }

    // 3) x_dbl = uconv @ W_xproj  [4096 x 96 x 2048]
    {
        dim3 grid((XD + BN - 1) / BN, M_TOT / BM);
        gemm_kernel<<<grid, blk>>>(uconv, W_xproj, xdbl,
                                   M_TOT, XD, D_INNER,
                                   D_INNER, XD, XD,
                                   nullptr, 0);
    }

    // 4) dt = softplus(dt_low @ W_dt + b_dt)  [4096 x 2048 x 64]
    {
        dim3 grid(D_INNER / BN, M_TOT / BM);
        gemm_kernel<<<grid, blk>>>(xdbl, W_dt, dtb,
                                   M_TOT, D_INNER, DT_RANK,
                                   XD, D_INNER, D_INNER,
                                   b_dt, 1);
    }

    // 5) selective scan
    {
        scan_kernel<<<(B_SZ * D_INNER) / 16, blk>>>(xdbl, dtb, uconv, A_log, yb);
    }

    // 6) combine
    {
        int total = M_TOT * D_INNER;
        combine_kernel<<<(total + 255) / 256, blk>>>(c1, uconv, Dp, yb);
    }

    // 7) out = y @ W_out  [4096 x 1024 x 2048]
    {
        dim3 grid(D_MODEL / BN, M_TOT / BM);
        gemm_kernel<<<grid, blk>>>(yb, W_out, out,
                                   M_TOT, D_MODEL, D_INNER,
                                   D_INNER, D_MODEL, D_MODEL,
                                   nullptr, 0);
    }
}

// round 8
// speedup vs baseline: 1.6026x; 1.3365x over previous
#include <cuda_runtime.h>
#include <cuda_bf16.h>
#include <math.h>
#include <stdint.h>

#define B_SZ     2
#define SEQ_L    2048
#define D_MODEL  1024
#define D_INNER  2048
#define D_STATE  16
#define D_CONV   4
#define DT_RANK  64
#define M_TOT    (B_SZ * SEQ_L)              // 4096
#define XD       (DT_RANK + 2 * D_STATE)     // 96

// ---------------------------------------------------------------------------
// Scratch (device globals)
// ---------------------------------------------------------------------------
__device__ float g_c1[(size_t)M_TOT * 2 * D_INNER];   // xr = [u_pre | res]
__device__ float g_uconv[(size_t)M_TOT * D_INNER];
__device__ float g_xdbl[(size_t)M_TOT * XD];
__device__ float g_dt[(size_t)M_TOT * D_INNER];
__device__ float g_y[(size_t)M_TOT * D_INNER];

// bf16 hi/lo split buffers
__device__ __nv_bfloat16 g_xh[(size_t)M_TOT * D_MODEL];
__device__ __nv_bfloat16 g_xl[(size_t)M_TOT * D_MODEL];
__device__ __nv_bfloat16 g_winth[(size_t)(2 * D_INNER) * D_MODEL]; // W_in^T
__device__ __nv_bfloat16 g_wintl[(size_t)(2 * D_INNER) * D_MODEL];
__device__ __nv_bfloat16 g_woutth[(size_t)D_MODEL * D_INNER];      // W_out^T
__device__ __nv_bfloat16 g_wouttl[(size_t)D_MODEL * D_INNER];
__device__ __nv_bfloat16 g_yh[(size_t)M_TOT * D_INNER];
__device__ __nv_bfloat16 g_yl[(size_t)M_TOT * D_INNER];

// ---------------------------------------------------------------------------
// Helpers (all baseline-PTX features: sm_80-class, no 'a' target needed)
// ---------------------------------------------------------------------------
__device__ __forceinline__ uint32_t smem_u32(const void* p) {
    uint32_t r;
    asm("{ .reg .u64 t; cvta.to.shared.u64 t, %1; cvt.u32.u64 %0, t; }"
        : "=r"(r) : "l"(p));
    return r;
}
__device__ __forceinline__ void cpa16(uint32_t dst, const void* src) {
    asm volatile("cp.async.cg.shared.global [%0], [%1], 16;"
                 :: "r"(dst), "l"(src) : "memory");
}
__device__ __forceinline__ void cpa_commit() {
    asm volatile("cp.async.commit_group;" ::: "memory");
}
__device__ __forceinline__ void cpa_wait1() {
    asm volatile("cp.async.wait_group 1;" ::: "memory");
}
__device__ __forceinline__ void cpa_wait0() {
    asm volatile("cp.async.wait_group 0;" ::: "memory");
}
__device__ __forceinline__ void ldm_x4(uint32_t a, uint32_t& r0, uint32_t& r1,
                                       uint32_t& r2, uint32_t& r3) {
    asm volatile("ldmatrix.sync.aligned.m8n8.x4.shared.b16 {%0,%1,%2,%3}, [%4];"
                 : "=r"(r0), "=r"(r1), "=r"(r2), "=r"(r3) : "r"(a));
}
__device__ __forceinline__ void mma_bf16(float& c0, float& c1, float& c2, float& c3,
                                         uint32_t a0, uint32_t a1, uint32_t a2, uint32_t a3,
                                         uint32_t b0, uint32_t b1) {
    asm volatile(
        "mma.sync.aligned.m16n8k16.row.col.f32.bf16.bf16.f32 "
        "{%0,%1,%2,%3}, {%4,%5,%6,%7}, {%8,%9}, {%0,%1,%2,%3};"
        : "+f"(c0), "+f"(c1), "+f"(c2), "+f"(c3)
        : "r"(a0), "r"(a1), "r"(a2), "r"(a3), "r"(b0), "r"(b1));
}

// ---------------------------------------------------------------------------
// Tensor-core GEMM (HMMA): C[M,N](fp32) = (Ah+Al)[M,K] @ (Bh+Bl)[N,K]^T
//   3-term split: ah*bh + ah*bl + al*bh. A,B bf16 row-major, ld = K.
//   CTA tile 128x128, BK=32, 8 warps (2x4), warp tile 64x32.
//   Requires M,N % 128 == 0, K % 32 == 0.
// ---------------------------------------------------------------------------
#define TROW   80                       // smem row stride in bytes (32+8 elems)
#define TTILE  (128 * TROW)             // 10240 B per operand tile
#define TBUF   (4 * TTILE)              // Ah,Al,Bh,Bl
#define TSMEM  (2 * TBUF)               // 81920 B double-buffered

// issue cp.async for one 128x32 operand tile
__device__ __forceinline__ void mm_load(const __nv_bfloat16* __restrict__ base,
                                        int K, int rowTile, int k0, uint32_t sdst)
{
    const int t = threadIdx.x;
    #pragma unroll
    for (int i = 0; i < 2; ++i) {
        const int idx = t + i * 256;            // 0..511
        const int row = idx >> 2;
        const int c16 = idx & 3;
        cpa16(sdst + row * TROW + c16 * 16,
              base + (size_t)(rowTile + row) * K + k0 + c16 * 8);
    }
}

__global__ __launch_bounds__(256, 1) void mm_gemm_kernel(
    const __nv_bfloat16* __restrict__ Ah, const __nv_bfloat16* __restrict__ Al,
    const __nv_bfloat16* __restrict__ Bh, const __nv_bfloat16* __restrict__ Bl,
    float* __restrict__ C, int M, int N, int K)
{
    extern __shared__ char dsm[];
    const uint32_t sb = smem_u32(dsm);

    const int tid  = threadIdx.x;
    const int lane = tid & 31;
    const int wid  = tid >> 5;
    const int wr   = wid >> 2;          // 0..1
    const int wc   = wid & 3;           // 0..3
    const int row0 = blockIdx.y * 128;
    const int col0 = blockIdx.x * 128;
    const int nch  = K >> 5;

    // lane-dependent ldmatrix offsets
    const int a_row  = lane & 15;           // row within 16
    const int a_koff = (lane >> 4) * 8;     // k half
    const int b_nrow = (lane & 7) + ((lane >> 4) & 1) * 8;
    const int b_koff = ((lane >> 3) & 1) * 8;

    float acc[4][4][4];
    #pragma unroll
    for (int i = 0; i < 4; i++)
        #pragma unroll
        for (int j = 0; j < 4; j++)
            #pragma unroll
            for (int e = 0; e < 4; e++) acc[i][j][e] = 0.0f;

    // prologue: chunk 0 -> buf 0
    mm_load(Ah, K, row0, 0, sb);
    mm_load(Al, K, row0, 0, sb + TTILE);
    mm_load(Bh, K, col0, 0, sb + 2 * TTILE);
    mm_load(Bl, K, col0, 0, sb + 3 * TTILE);
    cpa_commit();

    for (int c = 0; c < nch; ++c) {
        if (c + 1 < nch) {
            const uint32_t nb = sb + ((c + 1) & 1) * TBUF;
            const int ke = (c + 1) << 5;
            mm_load(Ah, K, row0, ke, nb);
            mm_load(Al, K, row0, ke, nb + TTILE);
            mm_load(Bh, K, col0, ke, nb + 2 * TTILE);
            mm_load(Bl, K, col0, ke, nb + 3 * TTILE);
            cpa_commit();
            cpa_wait1();
        } else {
            cpa_wait0();
        }
        __syncthreads();

        const uint32_t buf = sb + (c & 1) * TBUF;
        #pragma unroll
        for (int kk = 0; kk < 32; kk += 16) {
            uint32_t ah[4][4], al[4][4], bh[2][4], bl[2][4];
            #pragma unroll
            for (int mi = 0; mi < 4; ++mi) {
                const uint32_t ao = buf
                    + (uint32_t)(wr * 64 + mi * 16 + a_row) * TROW
                    + (uint32_t)(kk + a_koff) * 2;
                ldm_x4(ao,          ah[mi][0], ah[mi][1], ah[mi][2], ah[mi][3]);
                ldm_x4(ao + TTILE,  al[mi][0], al[mi][1], al[mi][2], al[mi][3]);
            }
            #pragma unroll
            for (int nb2 = 0; nb2 < 2; ++nb2) {
                const uint32_t bo = buf + 2 * TTILE
                    + (uint32_t)(wc * 32 + nb2 * 16 + b_nrow) * TROW
                    + (uint32_t)(kk + b_koff) * 2;
                ldm_x4(bo,          bh[nb2][0], bh[nb2][1], bh[nb2][2], bh[nb2][3]);
                ldm_x4(bo + TTILE,  bl[nb2][0], bl[nb2][1], bl[nb2][2], bl[nb2][3]);
            }
            #pragma unroll
            for (int mi = 0; mi < 4; ++mi) {
                #pragma unroll
                for (int ni = 0; ni < 4; ++ni) {
                    const int g = ni >> 1, h2 = (ni & 1) * 2;
                    // ah * bh
                    mma_bf16(acc[mi][ni][0], acc[mi][ni][1], acc[mi][ni][2], acc[mi][ni][3],
                             ah[mi][0], ah[mi][1], ah[mi][2], ah[mi][3],
                             bh[g][h2], bh[g][h2 + 1]);
                    // ah * bl
                    mma_bf16(acc[mi][ni][0], acc[mi][ni][1], acc[mi][ni][2], acc[mi][ni][3],
                             ah[mi][0], ah[mi][1], ah[mi][2], ah[mi][3],
                             bl[g][h2], bl[g][h2 + 1]);
                    // al * bh
                    mma_bf16(acc[mi][ni][0], acc[mi][ni][1], acc[mi][ni][2], acc[mi][ni][3],
                             al[mi][0], al[mi][1], al[mi][2], al[mi][3],
                             bh[g][h2], bh[g][h2 + 1]);
                }
            }
        }
        __syncthreads();
    }

    // epilogue
    const int gid = lane >> 2;
    const int t2  = (lane & 3) * 2;
    #pragma unroll
    for (int mi = 0; mi < 4; ++mi) {
        const int r = row0 + wr * 64 + mi * 16 + gid;
        #pragma unroll
        for (int ni = 0; ni < 4; ++ni) {
            const int cc = col0 + wc * 32 + ni * 8 + t2;
            *(float2*)(C + (size_t)r * N + cc) =
                make_float2(acc[mi][ni][0], acc[mi][ni][1]);
            *(float2*)(C + (size_t)(r + 8) * N + cc) =
                make_float2(acc[mi][ni][2], acc[mi][ni][3]);
        }
    }
}

// ---------------------------------------------------------------------------
// fp32 -> bf16 hi/lo split (elementwise)
// ---------------------------------------------------------------------------
__global__ void cvt_hilo_kernel(const float4* __restrict__ s,
                                __nv_bfloat162* __restrict__ h,
                                __nv_bfloat162* __restrict__ l, int n4)
{
    int i = blockIdx.x * blockDim.x + threadIdx.x;
    if (i >= n4) return;
    float4 v = s[i];
    __nv_bfloat16 hx = __float2bfloat16(v.x), hy = __float2bfloat16(v.y);
    __nv_bfloat16 hz = __float2bfloat16(v.z), hw = __float2bfloat16(v.w);
    h[2*i]   = __halves2bfloat162(hx, hy);
    h[2*i+1] = __halves2bfloat162(hz, hw);
    l[2*i]   = __halves2bfloat162(__float2bfloat16(v.x - __bfloat162float(hx)),
                                  __float2bfloat16(v.y - __bfloat162float(hy)));
    l[2*i+1] = __halves2bfloat162(__float2bfloat16(v.z - __bfloat162float(hz)),
                                  __float2bfloat16(v.w - __bfloat162float(hw)));
}

// ---------------------------------------------------------------------------
// Transpose + hi/lo split:  src[R, Cc] fp32 -> out[Cc, R] bf16 (hi, lo)
// ---------------------------------------------------------------------------
__global__ void cvt_t_kernel(const float* __restrict__ s,
                             __nv_bfloat16* __restrict__ h,
                             __nv_bfloat16* __restrict__ l, int R, int Cc)
{
    __shared__ float t[32][33];
    const int c0 = blockIdx.x * 32, r0 = blockIdx.y * 32;
    #pragma unroll
    for (int i = 0; i < 32; i += 8)
        t[threadIdx.y + i][threadIdx.x] =
            s[(size_t)(r0 + threadIdx.y + i) * Cc + c0 + threadIdx.x];
    __syncthreads();
    #pragma unroll
    for (int i = 0; i < 32; i += 8) {
        float v = t[threadIdx.x][threadIdx.y + i];
        __nv_bfloat16 hb = __float2bfloat16(v);
        size_t o = (size_t)(c0 + threadIdx.y + i) * R + r0 + threadIdx.x;
        h[o] = hb;
        l[o] = __float2bfloat16(v - __bfloat162float(hb));
    }
}

// ---------------------------------------------------------------------------
// fp32 SIMT GEMM (FFMA2) — small GEMMs (xproj, dt)
// ---------------------------------------------------------------------------
#define BM 128
#define BN 128
#define BK 16

__global__ __launch_bounds__(256) void gemm_kernel(
    const float* __restrict__ A, const float* __restrict__ B, float* __restrict__ C,
    int M, int N, int K, int lda, int ldb, int ldc,
    const float* __restrict__ bias, int mode)
{
    __shared__ float As[2][BK][BM];
    __shared__ float Bs[2][BK][BN];

    const int tid  = threadIdx.x;
    const int row0 = blockIdx.y * BM;
    const int col0 = blockIdx.x * BN;

    const int a_r = tid >> 2;
    const int a_c = (tid & 3) * 4;
    const int b_r = tid >> 5;
    const int b_c = (tid & 31) * 4;
    const int tr = (tid >> 4) * 4;
    const int tc = (tid & 15) * 4;

    unsigned long long acc[8][4];
    #pragma unroll
    for (int i = 0; i < 8; i++)
        #pragma unroll
        for (int j = 0; j < 4; j++) acc[i][j] = 0ull;

    const bool bok = (col0 + b_c) < N;
    const float* Ap0 = A + (size_t)(row0 + a_r) * lda + a_c;
    const float* Ap1 = Ap0 + (size_t)64 * lda;
    const float* Bp0 = B + (size_t)b_r * ldb + col0 + b_c;
    const float* Bp1 = Bp0 + (size_t)8 * ldb;

    float4 pa0, pa1, pb0, pb1;
    const float4 fz = make_float4(0.f, 0.f, 0.f, 0.f);

    pa0 = *(const float4*)(Ap0);
    pa1 = *(const float4*)(Ap1);
    pb0 = bok ? *(const float4*)(Bp0) : fz;
    pb1 = bok ? *(const float4*)(Bp1) : fz;
    {
        As[0][a_c + 0][a_r]      = pa0.x; As[0][a_c + 1][a_r]      = pa0.y;
        As[0][a_c + 2][a_r]      = pa0.z; As[0][a_c + 3][a_r]      = pa0.w;
        As[0][a_c + 0][a_r + 64] = pa1.x; As[0][a_c + 1][a_r + 64] = pa1.y;
        As[0][a_c + 2][a_r + 64] = pa1.z; As[0][a_c + 3][a_r + 64] = pa1.w;
        *(float4*)(&Bs[0][b_r][b_c])     = pb0;
        *(float4*)(&Bs[0][b_r + 8][b_c]) = pb1;
    }
    __syncthreads();

    int cur = 0;
    for (int k0 = BK; k0 < K; k0 += BK) {
        pa0 = *(const float4*)(Ap0 + k0);
        pa1 = *(const float4*)(Ap1 + k0);
        pb0 = bok ? *(const float4*)(Bp0 + (size_t)k0 * ldb) : fz;
        pb1 = bok ? *(const float4*)(Bp1 + (size_t)k0 * ldb) : fz;

        #pragma unroll
        for (int k = 0; k < BK; k++) {
            float4 a0 = *(const float4*)(&As[cur][k][tr]);
            float4 a1 = *(const float4*)(&As[cur][k][tr + 64]);
            float4 b0 = *(const float4*)(&Bs[cur][k][tc]);
            float4 b1 = *(const float4*)(&Bs[cur][k][tc + 64]);
            unsigned long long bb[4];
            bb[0] = *((const unsigned long long*)&b0 + 0);
            bb[1] = *((const unsigned long long*)&b0 + 1);
            bb[2] = *((const unsigned long long*)&b1 + 0);
            bb[3] = *((const unsigned long long*)&b1 + 1);
            float av[8] = {a0.x, a0.y, a0.z, a0.w, a1.x, a1.y, a1.z, a1.w};
            #pragma unroll
            for (int i = 0; i < 8; i++) {
                unsigned long long a2;
                asm("mov.b64 %0, {%1, %1};" : "=l"(a2) : "r"(__float_as_uint(av[i])));
                #pragma unroll
                for (int j = 0; j < 4; j++)
                    asm("fma.rn.f32x2 %0, %1, %2, %0;"
                        : "+l"(acc[i][j]) : "l"(a2), "l"(bb[j]));
            }
        }

        {
            int nb = cur ^ 1;
            As[nb][a_c + 0][a_r]      = pa0.x; As[nb][a_c + 1][a_r]      = pa0.y;
            As[nb][a_c + 2][a_r]      = pa0.z; As[nb][a_c + 3][a_r]      = pa0.w;
            As[nb][a_c + 0][a_r + 64] = pa1.x; As[nb][a_c + 1][a_r + 64] = pa1.y;
            As[nb][a_c + 2][a_r + 64] = pa1.z; As[nb][a_c + 3][a_r + 64] = pa1.w;
            *(float4*)(&Bs[nb][b_r][b_c])     = pb0;
            *(float4*)(&Bs[nb][b_r + 8][b_c]) = pb1;
        }
        __syncthreads();
        cur ^= 1;
    }

    #pragma unroll
    for (int k = 0; k < BK; k++) {
        float4 a0 = *(const float4*)(&As[cur][k][tr]);
        float4 a1 = *(const float4*)(&As[cur][k][tr + 64]);
        float4 b0 = *(const float4*)(&Bs[cur][k][tc]);
        float4 b1 = *(const float4*)(&Bs[cur][k][tc + 64]);
        unsigned long long bb[4];
        bb[0] = *((const unsigned long long*)&b0 + 0);
        bb[1] = *((const unsigned long long*)&b0 + 1);
        bb[2] = *((const unsigned long long*)&b1 + 0);
        bb[3] = *((const unsigned long long*)&b1 + 1);
        float av[8] = {a0.x, a0.y, a0.z, a0.w, a1.x, a1.y, a1.z, a1.w};
        #pragma unroll
        for (int i = 0; i < 8; i++) {
            unsigned long long a2;
            asm("mov.b64 %0, {%1, %1};" : "=l"(a2) : "r"(__float_as_uint(av[i])));
            #pragma unroll
            for (int j = 0; j < 4; j++)
                asm("fma.rn.f32x2 %0, %1, %2, %0;"
                    : "+l"(acc[i][j]) : "l"(a2), "l"(bb[j]));
        }
    }

    union F2 { unsigned long long u; float f[2]; };
    #pragma unroll
    for (int i = 0; i < 8; i++) {
        const int r = row0 + tr + ((i < 4) ? i : (60 + i));
        #pragma unroll
        for (int j2 = 0; j2 < 4; j2++) {
            const int cbase = col0 + ((j2 < 2) ? (tc + j2 * 2)
                                               : (tc + 64 + (j2 - 2) * 2));
            if (cbase < N) {
                F2 v; v.u = acc[i][j2];
                if (mode == 1) {
                    #pragma unroll
                    for (int e = 0; e < 2; e++) {
                        float val = v.f[e] + bias[cbase + e];
                        v.f[e] = (val > 20.0f) ? val : log1pf(__expf(val));
                    }
                }
                *(float2*)(C + (size_t)r * ldc + cbase) = make_float2(v.f[0], v.f[1]);
            }
        }
    }
}

// ---------------------------------------------------------------------------
// Causal depthwise conv4 + bias + silu
// ---------------------------------------------------------------------------
__global__ void conv_silu_kernel(const float* __restrict__ c1,
                                 const float* __restrict__ w,
                                 const float* __restrict__ bias,
                                 float* __restrict__ out)
{
    int idx = blockIdx.x * blockDim.x + threadIdx.x;
    if (idx >= M_TOT * D_INNER) return;
    const int d = idx & (D_INNER - 1);
    const int m = idx >> 11;
    const int l = m & (SEQ_L - 1);
    const float* up = c1 + (size_t)(m - l) * (2 * D_INNER) + d;
    float acc = bias[d];
    #pragma unroll
    for (int k = 0; k < D_CONV; k++) {
        int ll = l + k - (D_CONV - 1);
        if (ll >= 0)
            acc = fmaf(up[(size_t)ll * (2 * D_INNER)], w[d * D_CONV + k], acc);
    }
    out[idx] = acc * (1.0f / (1.0f + __expf(-acc)));
}

// ---------------------------------------------------------------------------
// Selective scan
// ---------------------------------------------------------------------------
__global__ __launch_bounds__(256) void scan_kernel(
    const float* __restrict__ xdbl, const float* __restrict__ dt,
    const float* __restrict__ u, const float* __restrict__ A_log,
    float* __restrict__ y)
{
    const int c = blockIdx.x * 16 + (threadIdx.x >> 4);
    const int s = threadIdx.x & 15;
    const int b = c >> 11;
    const int d = c & (D_INNER - 1);

    const float A = -__expf(A_log[d * D_STATE + s]);

    const float* dtp = dt   + (size_t)b * SEQ_L * D_INNER + d;
    const float* up  = u    + (size_t)b * SEQ_L * D_INNER + d;
    const float* xp  = xdbl + (size_t)b * SEQ_L * XD + DT_RANK + s;
    float*       yp  = y    + (size_t)b * SEQ_L * D_INNER + d;

    float h = 0.0f;
    float dtv = dtp[0];
    float uv  = up[0];
    float Bv  = xp[0];
    float Cv  = xp[D_STATE];
    float dA  = __expf(dtv * A);
    float dBu = dtv * Bv * uv;

    for (int l = 0; l < SEQ_L; l++) {
        float dt2 = 0.f, u2 = 0.f, B2 = 0.f, C2 = 0.f;
        if (l + 1 < SEQ_L) {
            size_t o = (size_t)(l + 1);
            dt2 = dtp[o * D_INNER];
            u2  = up [o * D_INNER];
            B2  = xp [o * XD];
            C2  = xp [o * XD + D_STATE];
        }
        h = fmaf(dA, h, dBu);
        float p = h * Cv;
        p += __shfl_xor_sync(0xffffffffu, p, 8);
        p += __shfl_xor_sync(0xffffffffu, p, 4);
        p += __shfl_xor_sync(0xffffffffu, p, 2);
        p += __shfl_xor_sync(0xffffffffu, p, 1);
        if (s == 0) yp[(size_t)l * D_INNER] = p;
        dA  = __expf(dt2 * A);
        dBu = dt2 * B2 * u2;
        Cv  = C2;
    }
}

// ---------------------------------------------------------------------------
// combine: v = (y_scan + u*D) * silu(res)  -> bf16 hi/lo for GEMM4
// ---------------------------------------------------------------------------
__global__ void combine_kernel(const float* __restrict__ c1,
                               const float* __restrict__ uconv,
                               const float* __restrict__ Dp,
                               const float* __restrict__ y,
                               __nv_bfloat16* __restrict__ yh,
                               __nv_bfloat16* __restrict__ yl)
{
    int idx = blockIdx.x * blockDim.x + threadIdx.x;
    if (idx >= M_TOT * D_INNER) return;
    const int d = idx & (D_INNER - 1);
    const int m = idx >> 11;
    const float res = c1[(size_t)m * (2 * D_INNER) + D_INNER + d];
    const float sres = res * (1.0f / (1.0f + __expf(-res)));
    const float v = (y[idx] + uconv[idx] * Dp[d]) * sres;
    __nv_bfloat16 hb = __float2bfloat16(v);
    yh[idx] = hb;
    yl[idx] = __float2bfloat16(v - __bfloat162float(hb));
}

// ---------------------------------------------------------------------------
// Launch
// ---------------------------------------------------------------------------
extern "C" void kernel_launch(void* const* d_in, const int* in_sizes, int n_in,
                              void* d_out, int out_size)
{
    const float* x       = (const float*)d_in[0];
    const float* W_in    = (const float*)d_in[1];
    const float* conv_w  = (const float*)d_in[2];
    const float* conv_b  = (const float*)d_in[3];
    const float* W_xproj = (const float*)d_in[4];
    const float* W_dt    = (const float*)d_in[5];
    const float* b_dt    = (const float*)d_in[6];
    const float* A_log   = (const float*)d_in[7];
    const float* Dp      = (const float*)d_in[8];
    const float* W_out   = (const float*)d_in[9];
    float* out = (float*)d_out;

    float *c1, *uconv, *xdbl, *dtb, *yb;
    __nv_bfloat16 *xh, *xl, *wth, *wtl, *woh, *wol, *yh, *yl;
    cudaGetSymbolAddress((void**)&c1,    g_c1);
    cudaGetSymbolAddress((void**)&uconv, g_uconv);
    cudaGetSymbolAddress((void**)&xdbl,  g_xdbl);
    cudaGetSymbolAddress((void**)&dtb,   g_dt);
    cudaGetSymbolAddress((void**)&yb,    g_y);
    cudaGetSymbolAddress((void**)&xh,    g_xh);
    cudaGetSymbolAddress((void**)&xl,    g_xl);
    cudaGetSymbolAddress((void**)&wth,   g_winth);
    cudaGetSymbolAddress((void**)&wtl,   g_wintl);
    cudaGetSymbolAddress((void**)&woh,   g_woutth);
    cudaGetSymbolAddress((void**)&wol,   g_wouttl);
    cudaGetSymbolAddress((void**)&yh,    g_yh);
    cudaGetSymbolAddress((void**)&yl,    g_yl);

    cudaFuncSetAttribute(mm_gemm_kernel,
                         cudaFuncAttributeMaxDynamicSharedMemorySize, TSMEM);

    dim3 blk(256);

    // 0) conversions
    {
        int n4 = (M_TOT * D_MODEL) / 4;
        cvt_hilo_kernel<<<(n4 + 255) / 256, blk>>>((const float4*)x,
                                                   (__nv_bfloat162*)xh,
                                                   (__nv_bfloat162*)xl, n4);
        dim3 tb(32, 8);
        cvt_t_kernel<<<dim3((2 * D_INNER) / 32, D_MODEL / 32), tb>>>(
            W_in, wth, wtl, D_MODEL, 2 * D_INNER);
        cvt_t_kernel<<<dim3(D_MODEL / 32, D_INNER / 32), tb>>>(
            W_out, woh, wol, D_INNER, D_MODEL);
    }

    // 1) xr = x @ W_in  (HMMA)  [4096 x 4096 x 1024]
    {
        dim3 grid((2 * D_INNER) / 128, M_TOT / 128);
        mm_gemm_kernel<<<grid, blk, TSMEM>>>(xh, xl, wth, wtl, c1,
                                             M_TOT, 2 * D_INNER, D_MODEL);
    }

    // 2) causal conv + silu
    {
        int total = M_TOT * D_INNER;
        conv_silu_kernel<<<(total + 255) / 256, blk>>>(c1, conv_w, conv_b, uconv);
    }

    // 3) x_dbl = uconv @ W_xproj  [4096 x 96 x 2048]
    {
        dim3 grid((XD + BN - 1) / BN, M_TOT / BM);
        gemm_kernel<<<grid, blk>>>(uconv, W_xproj, xdbl,
                                   M_TOT, XD, D_INNER,
                                   D_INNER, XD, XD, nullptr, 0);
    }

    // 4) dt = softplus(dt_low @ W_dt + b_dt)  [4096 x 2048 x 64]
    {
        dim3 grid(D_INNER / BN, M_TOT / BM);
        gemm_kernel<<<grid, blk>>>(xdbl, W_dt, dtb,
                                   M_TOT, D_INNER, DT_RANK,
                                   XD, D_INNER, D_INNER, b_dt, 1);
    }

    // 5) selective scan
    {
        scan_kernel<<<(B_SZ * D_INNER) / 16, blk>>>(xdbl, dtb, uconv, A_log, yb);
    }

    // 6) combine -> y hi/lo
    {
        int total = M_TOT * D_INNER;
        combine_kernel<<<(total + 255) / 256, blk>>>(c1, uconv, Dp, yb, yh, yl);
    }

    // 7) out = y @ W_out  (HMMA)  [4096 x 1024 x 2048]
    {
        dim3 grid(D_MODEL / 128, M_TOT / 128);
        mm_gemm_kernel<<<grid, blk, TSMEM>>>(yh, yl, woh, wol, out,
                                             M_TOT, D_MODEL, D_INNER);
    }
}

// round 9
// speedup vs baseline: 1.7518x; 1.0931x over previous
#include <cuda_runtime.h>
#include <cuda_bf16.h>
#include <math.h>
#include <stdint.h>

#define B_SZ     2
#define SEQ_L    2048
#define D_MODEL  1024
#define D_INNER  2048
#define D_STATE  16
#define D_CONV   4
#define DT_RANK  64
#define M_TOT    (B_SZ * SEQ_L)              // 4096
#define XD       (DT_RANK + 2 * D_STATE)     // 96
#define KSPLIT   8

// ---------------------------------------------------------------------------
// Scratch (device globals)
// ---------------------------------------------------------------------------
__device__ float g_c1[(size_t)M_TOT * 2 * D_INNER];   // xr = [u_pre | res]
__device__ float g_uconv[(size_t)M_TOT * D_INNER];
__device__ float g_xdbl[(size_t)M_TOT * XD];
__device__ float g_dt[(size_t)M_TOT * D_INNER];
__device__ float g_y[(size_t)M_TOT * D_INNER];
__device__ float g_part[(size_t)KSPLIT * M_TOT * XD]; // split-K partials

// bf16 hi/lo split buffers
__device__ __nv_bfloat16 g_xh[(size_t)M_TOT * D_MODEL];
__device__ __nv_bfloat16 g_xl[(size_t)M_TOT * D_MODEL];
__device__ __nv_bfloat16 g_winth[(size_t)(2 * D_INNER) * D_MODEL]; // W_in^T
__device__ __nv_bfloat16 g_wintl[(size_t)(2 * D_INNER) * D_MODEL];
__device__ __nv_bfloat16 g_woutth[(size_t)D_MODEL * D_INNER];      // W_out^T
__device__ __nv_bfloat16 g_wouttl[(size_t)D_MODEL * D_INNER];
__device__ __nv_bfloat16 g_yh[(size_t)M_TOT * D_INNER];
__device__ __nv_bfloat16 g_yl[(size_t)M_TOT * D_INNER];
__device__ __nv_bfloat16 g_uh[(size_t)M_TOT * D_INNER];            // silu(conv) hi
__device__ __nv_bfloat16 g_ul[(size_t)M_TOT * D_INNER];            // silu(conv) lo
__device__ __nv_bfloat16 g_wxth[(size_t)128 * D_INNER];            // W_xproj^T (pad 128)
__device__ __nv_bfloat16 g_wxtl[(size_t)128 * D_INNER];

// ---------------------------------------------------------------------------
// Helpers (baseline PTX only — no 'a'-target features)
// ---------------------------------------------------------------------------
__device__ __forceinline__ uint32_t smem_u32(const void* p) {
    uint32_t r;
    asm("{ .reg .u64 t; cvta.to.shared.u64 t, %1; cvt.u32.u64 %0, t; }"
        : "=r"(r) : "l"(p));
    return r;
}
__device__ __forceinline__ void cpa16(uint32_t dst, const void* src) {
    asm volatile("cp.async.cg.shared.global [%0], [%1], 16;"
                 :: "r"(dst), "l"(src) : "memory");
}
__device__ __forceinline__ void cpa_commit() {
    asm volatile("cp.async.commit_group;" ::: "memory");
}
__device__ __forceinline__ void cpa_wait1() {
    asm volatile("cp.async.wait_group 1;" ::: "memory");
}
__device__ __forceinline__ void cpa_wait0() {
    asm volatile("cp.async.wait_group 0;" ::: "memory");
}
__device__ __forceinline__ void ldm_x4(uint32_t a, uint32_t& r0, uint32_t& r1,
                                       uint32_t& r2, uint32_t& r3) {
    asm volatile("ldmatrix.sync.aligned.m8n8.x4.shared.b16 {%0,%1,%2,%3}, [%4];"
                 : "=r"(r0), "=r"(r1), "=r"(r2), "=r"(r3) : "r"(a));
}
__device__ __forceinline__ void mma_bf16(float& c0, float& c1, float& c2, float& c3,
                                         uint32_t a0, uint32_t a1, uint32_t a2, uint32_t a3,
                                         uint32_t b0, uint32_t b1) {
    asm volatile(
        "mma.sync.aligned.m16n8k16.row.col.f32.bf16.bf16.f32 "
        "{%0,%1,%2,%3}, {%4,%5,%6,%7}, {%8,%9}, {%0,%1,%2,%3};"
        : "+f"(c0), "+f"(c1), "+f"(c2), "+f"(c3)
        : "r"(a0), "r"(a1), "r"(a2), "r"(a3), "r"(b0), "r"(b1));
}

// ---------------------------------------------------------------------------
// Tensor-core GEMM (HMMA): C[M,*](fp32) = (Ah+Al)[M,K] @ (Bh+Bl)[N,K]^T
//   3-term split: ah*bh + ah*bl + al*bh. A,B bf16 row-major, ld = K.
//   CTA tile 128x128, BK=32, 8 warps (2x4), warp tile 64x32.
//   blockIdx.z = split-K segment (kpart K-elems each); partial z writes to
//   C + z*M*ldc. Stores guarded to col < nstore (row stride ldc).
// ---------------------------------------------------------------------------
#define TROW   80
#define TTILE  (128 * TROW)
#define TBUF   (4 * TTILE)
#define TSMEM  (2 * TBUF)

__device__ __forceinline__ void mm_load(const __nv_bfloat16* __restrict__ base,
                                        int K, int rowTile, int k0, uint32_t sdst)
{
    const int t = threadIdx.x;
    #pragma unroll
    for (int i = 0; i < 2; ++i) {
        const int idx = t + i * 256;
        const int row = idx >> 2;
        const int c16 = idx & 3;
        cpa16(sdst + row * TROW + c16 * 16,
              base + (size_t)(rowTile + row) * K + k0 + c16 * 8);
    }
}

__global__ __launch_bounds__(256, 2) void mm_gemm_kernel(
    const __nv_bfloat16* __restrict__ Ah, const __nv_bfloat16* __restrict__ Al,
    const __nv_bfloat16* __restrict__ Bh, const __nv_bfloat16* __restrict__ Bl,
    float* __restrict__ C, int M, int N, int K,
    int ldc, int nstore, int kpart)
{
    extern __shared__ char dsm[];
    const uint32_t sb = smem_u32(dsm);

    const int tid  = threadIdx.x;
    const int lane = tid & 31;
    const int wid  = tid >> 5;
    const int wr   = wid >> 2;
    const int wc   = wid & 3;
    const int row0 = blockIdx.y * 128;
    const int col0 = blockIdx.x * 128;
    const int kbase = blockIdx.z * kpart;
    const int nch  = kpart >> 5;
    if (gridDim.z > 1) C += (size_t)blockIdx.z * M * ldc;

    const int a_row  = lane & 15;
    const int a_koff = (lane >> 4) * 8;
    const int b_nrow = (lane & 7) + ((lane >> 4) & 1) * 8;
    const int b_koff = ((lane >> 3) & 1) * 8;

    float acc[4][4][4];
    #pragma unroll
    for (int i = 0; i < 4; i++)
        #pragma unroll
        for (int j = 0; j < 4; j++)
            #pragma unroll
            for (int e = 0; e < 4; e++) acc[i][j][e] = 0.0f;

    mm_load(Ah, K, row0, kbase, sb);
    mm_load(Al, K, row0, kbase, sb + TTILE);
    mm_load(Bh, K, col0, kbase, sb + 2 * TTILE);
    mm_load(Bl, K, col0, kbase, sb + 3 * TTILE);
    cpa_commit();

    for (int c = 0; c < nch; ++c) {
        if (c + 1 < nch) {
            const uint32_t nb = sb + ((c + 1) & 1) * TBUF;
            const int ke = kbase + ((c + 1) << 5);
            mm_load(Ah, K, row0, ke, nb);
            mm_load(Al, K, row0, ke, nb + TTILE);
            mm_load(Bh, K, col0, ke, nb + 2 * TTILE);
            mm_load(Bl, K, col0, ke, nb + 3 * TTILE);
            cpa_commit();
            cpa_wait1();
        } else {
            cpa_wait0();
        }
        __syncthreads();

        const uint32_t buf = sb + (c & 1) * TBUF;
        #pragma unroll
        for (int kk = 0; kk < 32; kk += 16) {
            uint32_t ah[4][4], al[4][4], bh[2][4], bl[2][4];
            #pragma unroll
            for (int mi = 0; mi < 4; ++mi) {
                const uint32_t ao = buf
                    + (uint32_t)(wr * 64 + mi * 16 + a_row) * TROW
                    + (uint32_t)(kk + a_koff) * 2;
                ldm_x4(ao,          ah[mi][0], ah[mi][1], ah[mi][2], ah[mi][3]);
                ldm_x4(ao + TTILE,  al[mi][0], al[mi][1], al[mi][2], al[mi][3]);
            }
            #pragma unroll
            for (int nb2 = 0; nb2 < 2; ++nb2) {
                const uint32_t bo = buf + 2 * TTILE
                    + (uint32_t)(wc * 32 + nb2 * 16 + b_nrow) * TROW
                    + (uint32_t)(kk + b_koff) * 2;
                ldm_x4(bo,          bh[nb2][0], bh[nb2][1], bh[nb2][2], bh[nb2][3]);
                ldm_x4(bo + TTILE,  bl[nb2][0], bl[nb2][1], bl[nb2][2], bl[nb2][3]);
            }
            #pragma unroll
            for (int mi = 0; mi < 4; ++mi) {
                #pragma unroll
                for (int ni = 0; ni < 4; ++ni) {
                    const int g = ni >> 1, h2 = (ni & 1) * 2;
                    mma_bf16(acc[mi][ni][0], acc[mi][ni][1], acc[mi][ni][2], acc[mi][ni][3],
                             ah[mi][0], ah[mi][1], ah[mi][2], ah[mi][3],
                             bh[g][h2], bh[g][h2 + 1]);
                    mma_bf16(acc[mi][ni][0], acc[mi][ni][1], acc[mi][ni][2], acc[mi][ni][3],
                             ah[mi][0], ah[mi][1], ah[mi][2], ah[mi][3],
                             bl[g][h2], bl[g][h2 + 1]);
                    mma_bf16(acc[mi][ni][0], acc[mi][ni][1], acc[mi][ni][2], acc[mi][ni][3],
                             al[mi][0], al[mi][1], al[mi][2], al[mi][3],
                             bh[g][h2], bh[g][h2 + 1]);
                }
            }
        }
        __syncthreads();
    }

    const int gid = lane >> 2;
    const int t2  = (lane & 3) * 2;
    #pragma unroll
    for (int mi = 0; mi < 4; ++mi) {
        const int r = row0 + wr * 64 + mi * 16 + gid;
        #pragma unroll
        for (int ni = 0; ni < 4; ++ni) {
            const int cc = col0 + wc * 32 + ni * 8 + t2;
            if (cc < nstore) {
                *(float2*)(C + (size_t)r * ldc + cc) =
                    make_float2(acc[mi][ni][0], acc[mi][ni][1]);
                *(float2*)(C + (size_t)(r + 8) * ldc + cc) =
                    make_float2(acc[mi][ni][2], acc[mi][ni][3]);
            }
        }
    }
}

// ---------------------------------------------------------------------------
// split-K reduce: out[i] = sum_z part[z*n + i]
// ---------------------------------------------------------------------------
__global__ void reduce_k_kernel(const float* __restrict__ part,
                                float* __restrict__ out, int n)
{
    int i = blockIdx.x * blockDim.x + threadIdx.x;
    if (i >= n) return;
    float s = 0.0f;
    #pragma unroll
    for (int z = 0; z < KSPLIT; ++z) s += part[(size_t)z * n + i];
    out[i] = s;
}

// ---------------------------------------------------------------------------
// fp32 -> bf16 hi/lo split (elementwise)
// ---------------------------------------------------------------------------
__global__ void cvt_hilo_kernel(const float4* __restrict__ s,
                                __nv_bfloat162* __restrict__ h,
                                __nv_bfloat162* __restrict__ l, int n4)
{
    int i = blockIdx.x * blockDim.x + threadIdx.x;
    if (i >= n4) return;
    float4 v = s[i];
    __nv_bfloat16 hx = __float2bfloat16(v.x), hy = __float2bfloat16(v.y);
    __nv_bfloat16 hz = __float2bfloat16(v.z), hw = __float2bfloat16(v.w);
    h[2*i]   = __halves2bfloat162(hx, hy);
    h[2*i+1] = __halves2bfloat162(hz, hw);
    l[2*i]   = __halves2bfloat162(__float2bfloat16(v.x - __bfloat162float(hx)),
                                  __float2bfloat16(v.y - __bfloat162float(hy)));
    l[2*i+1] = __halves2bfloat162(__float2bfloat16(v.z - __bfloat162float(hz)),
                                  __float2bfloat16(v.w - __bfloat162float(hw)));
}

// ---------------------------------------------------------------------------
// Transpose + hi/lo split:  src[*, Cc] fp32 -> out[Cc, R] bf16 (hi, lo)
// (R = number of src rows = output row stride)
// ---------------------------------------------------------------------------
__global__ void cvt_t_kernel(const float* __restrict__ s,
                             __nv_bfloat16* __restrict__ h,
                             __nv_bfloat16* __restrict__ l, int R, int Cc)
{
    __shared__ float t[32][33];
    const int c0 = blockIdx.x * 32, r0 = blockIdx.y * 32;
    #pragma unroll
    for (int i = 0; i < 32; i += 8)
        t[threadIdx.y + i][threadIdx.x] =
            s[(size_t)(r0 + threadIdx.y + i) * Cc + c0 + threadIdx.x];
    __syncthreads();
    #pragma unroll
    for (int i = 0; i < 32; i += 8) {
        float v = t[threadIdx.x][threadIdx.y + i];
        __nv_bfloat16 hb = __float2bfloat16(v);
        size_t o = (size_t)(c0 + threadIdx.y + i) * R + r0 + threadIdx.x;
        h[o] = hb;
        l[o] = __float2bfloat16(v - __bfloat162float(hb));
    }
}

// ---------------------------------------------------------------------------
// fp32 SIMT GEMM (FFMA2) — dt GEMM only (K=64)
// ---------------------------------------------------------------------------
#define BM 128
#define BN 128
#define BK 16

__global__ __launch_bounds__(256) void gemm_kernel(
    const float* __restrict__ A, const float* __restrict__ B, float* __restrict__ C,
    int M, int N, int K, int lda, int ldb, int ldc,
    const float* __restrict__ bias, int mode)
{
    __shared__ float As[2][BK][BM];
    __shared__ float Bs[2][BK][BN];

    const int tid  = threadIdx.x;
    const int row0 = blockIdx.y * BM;
    const int col0 = blockIdx.x * BN;

    const int a_r = tid >> 2;
    const int a_c = (tid & 3) * 4;
    const int b_r = tid >> 5;
    const int b_c = (tid & 31) * 4;
    const int tr = (tid >> 4) * 4;
    const int tc = (tid & 15) * 4;

    unsigned long long acc[8][4];
    #pragma unroll
    for (int i = 0; i < 8; i++)
        #pragma unroll
        for (int j = 0; j < 4; j++) acc[i][j] = 0ull;

    const bool bok = (col0 + b_c) < N;
    const float* Ap0 = A + (size_t)(row0 + a_r) * lda + a_c;
    const float* Ap1 = Ap0 + (size_t)64 * lda;
    const float* Bp0 = B + (size_t)b_r * ldb + col0 + b_c;
    const float* Bp1 = Bp0 + (size_t)8 * ldb;

    float4 pa0, pa1, pb0, pb1;
    const float4 fz = make_float4(0.f, 0.f, 0.f, 0.f);

    pa0 = *(const float4*)(Ap0);
    pa1 = *(const float4*)(Ap1);
    pb0 = bok ? *(const float4*)(Bp0) : fz;
    pb1 = bok ? *(const float4*)(Bp1) : fz;
    {
        As[0][a_c + 0][a_r]      = pa0.x; As[0][a_c + 1][a_r]      = pa0.y;
        As[0][a_c + 2][a_r]      = pa0.z; As[0][a_c + 3][a_r]      = pa0.w;
        As[0][a_c + 0][a_r + 64] = pa1.x; As[0][a_c + 1][a_r + 64] = pa1.y;
        As[0][a_c + 2][a_r + 64] = pa1.z; As[0][a_c + 3][a_r + 64] = pa1.w;
        *(float4*)(&Bs[0][b_r][b_c])     = pb0;
        *(float4*)(&Bs[0][b_r + 8][b_c]) = pb1;
    }
    __syncthreads();

    int cur = 0;
    for (int k0 = BK; k0 < K; k0 += BK) {
        pa0 = *(const float4*)(Ap0 + k0);
        pa1 = *(const float4*)(Ap1 + k0);
        pb0 = bok ? *(const float4*)(Bp0 + (size_t)k0 * ldb) : fz;
        pb1 = bok ? *(const float4*)(Bp1 + (size_t)k0 * ldb) : fz;

        #pragma unroll
        for (int k = 0; k < BK; k++) {
            float4 a0 = *(const float4*)(&As[cur][k][tr]);
            float4 a1 = *(const float4*)(&As[cur][k][tr + 64]);
            float4 b0 = *(const float4*)(&Bs[cur][k][tc]);
            float4 b1 = *(const float4*)(&Bs[cur][k][tc + 64]);
            unsigned long long bb[4];
            bb[0] = *((const unsigned long long*)&b0 + 0);
            bb[1] = *((const unsigned long long*)&b0 + 1);
            bb[2] = *((const unsigned long long*)&b1 + 0);
            bb[3] = *((const unsigned long long*)&b1 + 1);
            float av[8] = {a0.x, a0.y, a0.z, a0.w, a1.x, a1.y, a1.z, a1.w};
            #pragma unroll
            for (int i = 0; i < 8; i++) {
                unsigned long long a2;
                asm("mov.b64 %0, {%1, %1};" : "=l"(a2) : "r"(__float_as_uint(av[i])));
                #pragma unroll
                for (int j = 0; j < 4; j++)
                    asm("fma.rn.f32x2 %0, %1, %2, %0;"
                        : "+l"(acc[i][j]) : "l"(a2), "l"(bb[j]));
            }
        }

        {
            int nb = cur ^ 1;
            As[nb][a_c + 0][a_r]      = pa0.x; As[nb][a_c + 1][a_r]      = pa0.y;
            As[nb][a_c + 2][a_r]      = pa0.z; As[nb][a_c + 3][a_r]      = pa0.w;
            As[nb][a_c + 0][a_r + 64] = pa1.x; As[nb][a_c + 1][a_r + 64] = pa1.y;
            As[nb][a_c + 2][a_r + 64] = pa1.z; As[nb][a_c + 3][a_r + 64] = pa1.w;
            *(float4*)(&Bs[nb][b_r][b_c])     = pb0;
            *(float4*)(&Bs[nb][b_r + 8][b_c]) = pb1;
        }
        __syncthreads();
        cur ^= 1;
    }

    #pragma unroll
    for (int k = 0; k < BK; k++) {
        float4 a0 = *(const float4*)(&As[cur][k][tr]);
        float4 a1 = *(const float4*)(&As[cur][k][tr + 64]);
        float4 b0 = *(const float4*)(&Bs[cur][k][tc]);
        float4 b1 = *(const float4*)(&Bs[cur][k][tc + 64]);
        unsigned long long bb[4];
        bb[0] = *((const unsigned long long*)&b0 + 0);
        bb[1] = *((const unsigned long long*)&b0 + 1);
        bb[2] = *((const unsigned long long*)&b1 + 0);
        bb[3] = *((const unsigned long long*)&b1 + 1);
        float av[8] = {a0.x, a0.y, a0.z, a0.w, a1.x, a1.y, a1.z, a1.w};
        #pragma unroll
        for (int i = 0; i < 8; i++) {
            unsigned long long a2;
            asm("mov.b64 %0, {%1, %1};" : "=l"(a2) : "r"(__float_as_uint(av[i])));
            #pragma unroll
            for (int j = 0; j < 4; j++)
                asm("fma.rn.f32x2 %0, %1, %2, %0;"
                    : "+l"(acc[i][j]) : "l"(a2), "l"(bb[j]));
        }
    }

    union F2 { unsigned long long u; float f[2]; };
    #pragma unroll
    for (int i = 0; i < 8; i++) {
        const int r = row0 + tr + ((i < 4) ? i : (60 + i));
        #pragma unroll
        for (int j2 = 0; j2 < 4; j2++) {
            const int cbase = col0 + ((j2 < 2) ? (tc + j2 * 2)
                                               : (tc + 64 + (j2 - 2) * 2));
            if (cbase < N) {
                F2 v; v.u = acc[i][j2];
                if (mode == 1) {
                    #pragma unroll
                    for (int e = 0; e < 2; e++) {
                        float val = v.f[e] + bias[cbase + e];
                        v.f[e] = (val > 20.0f) ? val : log1pf(__expf(val));
                    }
                }
                *(float2*)(C + (size_t)r * ldc + cbase) = make_float2(v.f[0], v.f[1]);
            }
        }
    }
}

// ---------------------------------------------------------------------------
// Causal depthwise conv4 + bias + silu  (+ fused bf16 hi/lo split)
// ---------------------------------------------------------------------------
__global__ void conv_silu_kernel(const float* __restrict__ c1,
                                 const float* __restrict__ w,
                                 const float* __restrict__ bias,
                                 float* __restrict__ out,
                                 __nv_bfloat16* __restrict__ uh,
                                 __nv_bfloat16* __restrict__ ul)
{
    int idx = blockIdx.x * blockDim.x + threadIdx.x;
    if (idx >= M_TOT * D_INNER) return;
    const int d = idx & (D_INNER - 1);
    const int m = idx >> 11;
    const int l = m & (SEQ_L - 1);
    const float* up = c1 + (size_t)(m - l) * (2 * D_INNER) + d;
    float acc = bias[d];
    #pragma unroll
    for (int k = 0; k < D_CONV; k++) {
        int ll = l + k - (D_CONV - 1);
        if (ll >= 0)
            acc = fmaf(up[(size_t)ll * (2 * D_INNER)], w[d * D_CONV + k], acc);
    }
    const float v = acc * (1.0f / (1.0f + __expf(-acc)));
    out[idx] = v;
    __nv_bfloat16 hb = __float2bfloat16(v);
    uh[idx] = hb;
    ul[idx] = __float2bfloat16(v - __bfloat162float(hb));
}

// ---------------------------------------------------------------------------
// Selective scan
// ---------------------------------------------------------------------------
__global__ __launch_bounds__(256) void scan_kernel(
    const float* __restrict__ xdbl, const float* __restrict__ dt,
    const float* __restrict__ u, const float* __restrict__ A_log,
    float* __restrict__ y)
{
    const int c = blockIdx.x * 16 + (threadIdx.x >> 4);
    const int s = threadIdx.x & 15;
    const int b = c >> 11;
    const int d = c & (D_INNER - 1);

    const float A = -__expf(A_log[d * D_STATE + s]);

    const float* dtp = dt   + (size_t)b * SEQ_L * D_INNER + d;
    const float* up  = u    + (size_t)b * SEQ_L * D_INNER + d;
    const float* xp  = xdbl + (size_t)b * SEQ_L * XD + DT_RANK + s;
    float*       yp  = y    + (size_t)b * SEQ_L * D_INNER + d;

    float h = 0.0f;
    float dtv = dtp[0];
    float uv  = up[0];
    float Bv  = xp[0];
    float Cv  = xp[D_STATE];
    float dA  = __expf(dtv * A);
    float dBu = dtv * Bv * uv;

    for (int l = 0; l < SEQ_L; l++) {
        float dt2 = 0.f, u2 = 0.f, B2 = 0.f, C2 = 0.f;
        if (l + 1 < SEQ_L) {
            size_t o = (size_t)(l + 1);
            dt2 = dtp[o * D_INNER];
            u2  = up [o * D_INNER];
            B2  = xp [o * XD];
            C2  = xp [o * XD + D_STATE];
        }
        h = fmaf(dA, h, dBu);
        float p = h * Cv;
        p += __shfl_xor_sync(0xffffffffu, p, 8);
        p += __shfl_xor_sync(0xffffffffu, p, 4);
        p += __shfl_xor_sync(0xffffffffu, p, 2);
        p += __shfl_xor_sync(0xffffffffu, p, 1);
        if (s == 0) yp[(size_t)l * D_INNER] = p;
        dA  = __expf(dt2 * A);
        dBu = dt2 * B2 * u2;
        Cv  = C2;
    }
}

// ---------------------------------------------------------------------------
// combine: v = (y_scan + u*D) * silu(res)  -> bf16 hi/lo for GEMM4
// ---------------------------------------------------------------------------
__global__ void combine_kernel(const float* __restrict__ c1,
                               const float* __restrict__ uconv,
                               const float* __restrict__ Dp,
                               const float* __restrict__ y,
                               __nv_bfloat16* __restrict__ yh,
                               __nv_bfloat16* __restrict__ yl)
{
    int idx = blockIdx.x * blockDim.x + threadIdx.x;
    if (idx >= M_TOT * D_INNER) return;
    const int d = idx & (D_INNER - 1);
    const int m = idx >> 11;
    const float res = c1[(size_t)m * (2 * D_INNER) + D_INNER + d];
    const float sres = res * (1.0f / (1.0f + __expf(-res)));
    const float v = (y[idx] + uconv[idx] * Dp[d]) * sres;
    __nv_bfloat16 hb = __float2bfloat16(v);
    yh[idx] = hb;
    yl[idx] = __float2bfloat16(v - __bfloat162float(hb));
}

// ---------------------------------------------------------------------------
// Launch
// ---------------------------------------------------------------------------
extern "C" void kernel_launch(void* const* d_in, const int* in_sizes, int n_in,
                              void* d_out, int out_size)
{
    const float* x       = (const float*)d_in[0];
    const float* W_in    = (const float*)d_in[1];
    const float* conv_w  = (const float*)d_in[2];
    const float* conv_b  = (const float*)d_in[3];
    const float* W_xproj = (const float*)d_in[4];
    const float* W_dt    = (const float*)d_in[5];
    const float* b_dt    = (const float*)d_in[6];
    const float* A_log   = (const float*)d_in[7];
    const float* Dp      = (const float*)d_in[8];
    const float* W_out   = (const float*)d_in[9];
    float* out = (float*)d_out;

    float *c1, *uconv, *xdbl, *dtb, *yb, *part;
    __nv_bfloat16 *xh, *xl, *wth, *wtl, *woh, *wol, *yh, *yl, *uh, *ul, *wxh, *wxl;
    cudaGetSymbolAddress((void**)&c1,    g_c1);
    cudaGetSymbolAddress((void**)&uconv, g_uconv);
    cudaGetSymbolAddress((void**)&xdbl,  g_xdbl);
    cudaGetSymbolAddress((void**)&dtb,   g_dt);
    cudaGetSymbolAddress((void**)&yb,    g_y);
    cudaGetSymbolAddress((void**)&part,  g_part);
    cudaGetSymbolAddress((void**)&xh,    g_xh);
    cudaGetSymbolAddress((void**)&xl,    g_xl);
    cudaGetSymbolAddress((void**)&wth,   g_winth);
    cudaGetSymbolAddress((void**)&wtl,   g_wintl);
    cudaGetSymbolAddress((void**)&woh,   g_woutth);
    cudaGetSymbolAddress((void**)&wol,   g_wouttl);
    cudaGetSymbolAddress((void**)&yh,    g_yh);
    cudaGetSymbolAddress((void**)&yl,    g_yl);
    cudaGetSymbolAddress((void**)&uh,    g_uh);
    cudaGetSymbolAddress((void**)&ul,    g_ul);
    cudaGetSymbolAddress((void**)&wxh,   g_wxth);
    cudaGetSymbolAddress((void**)&wxl,   g_wxtl);

    cudaFuncSetAttribute(mm_gemm_kernel,
                         cudaFuncAttributeMaxDynamicSharedMemorySize, TSMEM);

    dim3 blk(256);

    // 0) conversions
    {
        int n4 = (M_TOT * D_MODEL) / 4;
        cvt_hilo_kernel<<<(n4 + 255) / 256, blk>>>((const float4*)x,
                                                   (__nv_bfloat162*)xh,
                                                   (__nv_bfloat162*)xl, n4);
        dim3 tb(32, 8);
        cvt_t_kernel<<<dim3((2 * D_INNER) / 32, D_MODEL / 32), tb>>>(
            W_in, wth, wtl, D_MODEL, 2 * D_INNER);
        cvt_t_kernel<<<dim3(D_MODEL / 32, D_INNER / 32), tb>>>(
            W_out, woh, wol, D_INNER, D_MODEL);
        // W_xproj [2048, 96] -> [96, 2048] hi/lo (padded buffer rows 96..127 unused)
        cvt_t_kernel<<<dim3(XD / 32, D_INNER / 32), tb>>>(
            W_xproj, wxh, wxl, D_INNER, XD);
    }

    // 1) xr = x @ W_in  (HMMA)  [4096 x 4096 x 1024]
    {
        dim3 grid((2 * D_INNER) / 128, M_TOT / 128, 1);
        mm_gemm_kernel<<<grid, blk, TSMEM>>>(xh, xl, wth, wtl, c1,
                                             M_TOT, 2 * D_INNER, D_MODEL,
                                             2 * D_INNER, 2 * D_INNER, D_MODEL);
    }

    // 2) causal conv + silu (+ hi/lo split)
    {
        int total = M_TOT * D_INNER;
        conv_silu_kernel<<<(total + 255) / 256, blk>>>(c1, conv_w, conv_b,
                                                       uconv, uh, ul);
    }

    // 3) x_dbl = uconv @ W_xproj  (HMMA split-K)  [4096 x 96 x 2048]
    {
        dim3 grid(1, M_TOT / 128, KSPLIT);
        mm_gemm_kernel<<<grid, blk, TSMEM>>>(uh, ul, wxh, wxl, part,
                                             M_TOT, 128, D_INNER,
                                             XD, XD, D_INNER / KSPLIT);
        int n = M_TOT * XD;
        reduce_k_kernel<<<(n + 255) / 256, blk>>>(part, xdbl, n);
    }

    // 4) dt = softplus(dt_low @ W_dt + b_dt)  [4096 x 2048 x 64]
    {
        dim3 grid(D_INNER / BN, M_TOT / BM);
        gemm_kernel<<<grid, blk>>>(xdbl, W_dt, dtb,
                                   M_TOT, D_INNER, DT_RANK,
                                   XD, D_INNER, D_INNER, b_dt, 1);
    }

    // 5) selective scan
    {
        scan_kernel<<<(B_SZ * D_INNER) / 16, blk>>>(xdbl, dtb, uconv, A_log, yb);
    }

    // 6) combine -> y hi/lo
    {
        int total = M_TOT * D_INNER;
        combine_kernel<<<(total + 255) / 256, blk>>>(c1, uconv, Dp, yb, yh, yl);
    }

    // 7) out = y @ W_out  (HMMA)  [4096 x 1024 x 2048]
    {
        dim3 grid(D_MODEL / 128, M_TOT / 128, 1);
        mm_gemm_kernel<<<grid, blk, TSMEM>>>(yh, yl, woh, wol, out,
                                             M_TOT, D_MODEL, D_INNER,
                                             D_MODEL, D_MODEL, D_INNER);
    }
}